// round 1
// baseline (speedup 1.0000x reference)
#include <cuda_runtime.h>
#include <cuda_bf16.h>
#include <cstdint>

// PairwiseRepresentation: masked periodic pairwise distances.
//   positions      [B,N,3]   f32
//   neighbors      [B,N,K]   i32
//   neighbor_mask  [B,N,K]   f32
//   cell           [B,3,3]   f32
//   cell_offsets   [B,N,K,3] f32
//   out            [B,N,K]   f32
//
// out[b,n,k] = mask ? || pos[b,nbr] - pos[b,n] + off @ cell[b] || : 0
//
// Layout: one warp per (b,n) row; each lane handles 4 consecutive k.
// All streaming accesses are 128-bit vectorized and fully coalesced.

__global__ __launch_bounds__(256)
void pairwise_dist_kernel(const float*  __restrict__ positions,
                          const int*    __restrict__ neighbors,
                          const float*  __restrict__ mask,
                          const float*  __restrict__ cell,
                          const float*  __restrict__ offsets,
                          float*        __restrict__ out,
                          int N, int K, int n_rows)
{
    const int warp_in_blk = threadIdx.x >> 5;
    const int lane        = threadIdx.x & 31;
    const int row         = blockIdx.x * (blockDim.x >> 5) + warp_in_blk; // b*N + n
    if (row >= n_rows) return;

    const int b = row / N;

    // --- broadcast loads (L1 hits across the warp) ---
    const float pix = __ldg(&positions[row * 3 + 0]);
    const float piy = __ldg(&positions[row * 3 + 1]);
    const float piz = __ldg(&positions[row * 3 + 2]);

    const float* cb = cell + b * 9;
    const float c00 = __ldg(&cb[0]), c01 = __ldg(&cb[1]), c02 = __ldg(&cb[2]);
    const float c10 = __ldg(&cb[3]), c11 = __ldg(&cb[4]), c12 = __ldg(&cb[5]);
    const float c20 = __ldg(&cb[6]), c21 = __ldg(&cb[7]), c22 = __ldg(&cb[8]);

    // --- vectorized streaming loads: 4 k's per lane ---
    const long base  = (long)row * K + lane * 4;          // element index into [B,N,K]
    const int4   nb4 = __ldg((const int4*)  (neighbors + base));
    const float4 mk4 = __ldg((const float4*)(mask      + base));

    const float* offp = offsets + base * 3;               // 12 floats, 16B-aligned
    const float4 o0 = __ldg((const float4*)(offp + 0));   // k0.xyz k1.x
    const float4 o1 = __ldg((const float4*)(offp + 4));   // k1.yz  k2.xy
    const float4 o2 = __ldg((const float4*)(offp + 8));   // k2.z   k3.xyz

    const float ox[4] = { o0.x, o0.w, o1.z, o2.y };
    const float oy[4] = { o0.y, o1.x, o1.w, o2.z };
    const float oz[4] = { o0.z, o1.y, o2.x, o2.w };
    const int   jj[4] = { nb4.x, nb4.y, nb4.z, nb4.w };
    const float mm[4] = { mk4.x, mk4.y, mk4.z, mk4.w };

    const float* posb = positions + (long)b * N * 3;

    float res[4];
#pragma unroll
    for (int t = 0; t < 4; ++t) {
        const float* pj = posb + (long)jj[t] * 3;          // gather: L1/L2 resident
        float dx = __ldg(&pj[0]) - pix;
        float dy = __ldg(&pj[1]) - piy;
        float dz = __ldg(&pj[2]) - piz;
        // periodic correction: off (row vec) @ cell
        dx = fmaf(ox[t], c00, fmaf(oy[t], c10, fmaf(oz[t], c20, dx)));
        dy = fmaf(ox[t], c01, fmaf(oy[t], c11, fmaf(oz[t], c21, dy)));
        dz = fmaf(ox[t], c02, fmaf(oy[t], c12, fmaf(oz[t], c22, dz)));
        const float sq = fmaf(dx, dx, fmaf(dy, dy, dz * dz));
        res[t] = (mm[t] > 0.0f) ? sqrtf(sq) : 0.0f;
    }

    float4 r4 = make_float4(res[0], res[1], res[2], res[3]);
    *((float4*)(out + base)) = r4;
}

extern "C" void kernel_launch(void* const* d_in, const int* in_sizes, int n_in,
                              void* d_out, int out_size)
{
    const float* positions = (const float*)d_in[0];
    const int*   neighbors = (const int*)  d_in[1];
    const float* mask      = (const float*)d_in[2];
    const float* cell      = (const float*)d_in[3];
    const float* offsets   = (const float*)d_in[4];
    float*       out       = (float*)d_out;

    // Derive shapes: cell = B*9, positions = B*N*3, neighbors = B*N*K
    const int B      = in_sizes[3] / 9;
    const int n_rows = in_sizes[0] / 3;      // B*N
    const int N      = n_rows / B;
    const int K      = in_sizes[1] / n_rows; // 128

    // 8 warps (rows) per 256-thread block
    const int rows_per_blk = 256 / 32;
    const int grid = (n_rows + rows_per_blk - 1) / rows_per_blk;

    pairwise_dist_kernel<<<grid, 256>>>(positions, neighbors, mask, cell,
                                        offsets, out, N, K, n_rows);
}

// round 2
// speedup vs baseline: 1.1635x; 1.1635x over previous
#include <cuda_runtime.h>
#include <cuda_bf16.h>
#include <cstdint>

// PairwiseRepresentation: masked periodic pairwise distances.
//   positions      [B,N,3]   f32
//   neighbors      [B,N,K]   i32
//   neighbor_mask  [B,N,K]   f32
//   cell           [B,3,3]   f32
//   cell_offsets   [B,N,K,3] f32
//   out            [B,N,K]   f32
//
// R2 change: positions are pre-padded into a float4-aligned scratch table so
// the random gather is ONE LDG.128 per neighbor instead of three LDG.32 —
// ~3x fewer L1 wavefronts on the gather path (the R1 bottleneck at 71.8% L1).
// Streaming loads/stores use .cs (evict-first) so the 1MB position table
// stays cache-resident.

#define MAX_ROWS (16 * 4096)   // B*N for this problem
__device__ float4 g_pos4[MAX_ROWS];   // 1 MB static scratch (allowed)

__global__ __launch_bounds__(256)
void pad_positions_kernel(const float* __restrict__ positions, int n_rows)
{
    int i = blockIdx.x * blockDim.x + threadIdx.x;
    if (i < n_rows && i < MAX_ROWS) {
        g_pos4[i] = make_float4(positions[i * 3 + 0],
                                positions[i * 3 + 1],
                                positions[i * 3 + 2], 0.0f);
    }
}

__global__ __launch_bounds__(256)
void pairwise_dist_kernel(const float*  __restrict__ positions,
                          const int*    __restrict__ neighbors,
                          const float*  __restrict__ mask,
                          const float*  __restrict__ cell,
                          const float*  __restrict__ offsets,
                          float*        __restrict__ out,
                          int N, int K, int n_rows)
{
    const int warp_in_blk = threadIdx.x >> 5;
    const int lane        = threadIdx.x & 31;
    const int row         = blockIdx.x * (blockDim.x >> 5) + warp_in_blk; // b*N + n
    if (row >= n_rows) return;

    const int b = row / N;

    // --- broadcast loads (L1 hits across the warp) ---
    const float4 pi4 = __ldg(&g_pos4[row]);
    const float pix = pi4.x, piy = pi4.y, piz = pi4.z;

    const float* cb = cell + b * 9;
    const float c00 = __ldg(&cb[0]), c01 = __ldg(&cb[1]), c02 = __ldg(&cb[2]);
    const float c10 = __ldg(&cb[3]), c11 = __ldg(&cb[4]), c12 = __ldg(&cb[5]);
    const float c20 = __ldg(&cb[6]), c21 = __ldg(&cb[7]), c22 = __ldg(&cb[8]);

    // --- vectorized streaming loads (evict-first): 4 k's per lane ---
    const long base  = (long)row * K + lane * 4;          // element index into [B,N,K]
    const int4   nb4 = __ldcs((const int4*)  (neighbors + base));
    const float4 mk4 = __ldcs((const float4*)(mask      + base));

    const float* offp = offsets + base * 3;               // 12 floats, 16B-aligned
    const float4 o0 = __ldcs((const float4*)(offp + 0));  // k0.xyz k1.x
    const float4 o1 = __ldcs((const float4*)(offp + 4));  // k1.yz  k2.xy
    const float4 o2 = __ldcs((const float4*)(offp + 8));  // k2.z   k3.xyz

    const float ox[4] = { o0.x, o0.w, o1.z, o2.y };
    const float oy[4] = { o0.y, o1.x, o1.w, o2.z };
    const float oz[4] = { o0.z, o1.y, o2.x, o2.w };
    const int   jj[4] = { nb4.x, nb4.y, nb4.z, nb4.w };
    const float mm[4] = { mk4.x, mk4.y, mk4.z, mk4.w };

    const float4* posb4 = g_pos4 + (long)b * N;

    // Issue all 4 gathers up front (MLP) before consuming.
    float4 pj[4];
#pragma unroll
    for (int t = 0; t < 4; ++t)
        pj[t] = __ldg(&posb4[jj[t]]);                      // single LDG.128 gather

    float res[4];
#pragma unroll
    for (int t = 0; t < 4; ++t) {
        float dx = pj[t].x - pix;
        float dy = pj[t].y - piy;
        float dz = pj[t].z - piz;
        // periodic correction: off (row vec) @ cell
        dx = fmaf(ox[t], c00, fmaf(oy[t], c10, fmaf(oz[t], c20, dx)));
        dy = fmaf(ox[t], c01, fmaf(oy[t], c11, fmaf(oz[t], c21, dy)));
        dz = fmaf(ox[t], c02, fmaf(oy[t], c12, fmaf(oz[t], c22, dz)));
        const float sq = fmaf(dx, dx, fmaf(dy, dy, dz * dz));
        res[t] = (mm[t] > 0.0f) ? sqrtf(sq) : 0.0f;
    }

    float4 r4 = make_float4(res[0], res[1], res[2], res[3]);
    __stcs((float4*)(out + base), r4);                     // evict-first store
}

extern "C" void kernel_launch(void* const* d_in, const int* in_sizes, int n_in,
                              void* d_out, int out_size)
{
    const float* positions = (const float*)d_in[0];
    const int*   neighbors = (const int*)  d_in[1];
    const float* mask      = (const float*)d_in[2];
    const float* cell      = (const float*)d_in[3];
    const float* offsets   = (const float*)d_in[4];
    float*       out       = (float*)d_out;

    // Derive shapes: cell = B*9, positions = B*N*3, neighbors = B*N*K
    const int B      = in_sizes[3] / 9;
    const int n_rows = in_sizes[0] / 3;      // B*N
    const int N      = n_rows / B;
    const int K      = in_sizes[1] / n_rows; // 128

    // Prologue: pad positions to float4 scratch.
    pad_positions_kernel<<<(n_rows + 255) / 256, 256>>>(positions, n_rows);

    // 8 warps (rows) per 256-thread block
    const int rows_per_blk = 256 / 32;
    const int grid = (n_rows + rows_per_blk - 1) / rows_per_blk;

    pairwise_dist_kernel<<<grid, 256>>>(positions, neighbors, mask, cell,
                                        offsets, out, N, K, n_rows);
}

// round 3
// speedup vs baseline: 1.1968x; 1.0285x over previous
#include <cuda_runtime.h>
#include <cuda_bf16.h>
#include <cstdint>

// PairwiseRepresentation: masked periodic pairwise distances.
//   positions      [B,N,3]   f32
//   neighbors      [B,N,K]   i32
//   neighbor_mask  [B,N,K]   f32
//   cell           [B,3,3]   f32
//   cell_offsets   [B,N,K,3] f32
//   out            [B,N,K]   f32
//
// R3: the random position gather moves from global (L1 wavefront path,
// ~32 wavefronts/instr) into a per-batch SMEM table (random LDS.128,
// ~8 cyc/instr). Each CTA owns one batch: loads the 64KB float4 table
// once, then streams ~152 rows. grid=(27,16) = 432 CTAs = one full wave
// at 3 CTAs/SM (64KB smem each).

#define MAX_ROWS (16 * 4096)
__device__ float4 g_pos4[MAX_ROWS];   // padded position table (1 MB scratch)

__global__ __launch_bounds__(256)
void pad_positions_kernel(const float* __restrict__ positions, int n_rows)
{
    int i = blockIdx.x * blockDim.x + threadIdx.x;
    if (i < n_rows && i < MAX_ROWS) {
        g_pos4[i] = make_float4(positions[i * 3 + 0],
                                positions[i * 3 + 1],
                                positions[i * 3 + 2], 0.0f);
    }
}

// ---------------- main kernel: smem position table ----------------
__global__ __launch_bounds__(256, 3)
void pairwise_smem_kernel(const int*    __restrict__ neighbors,
                          const float*  __restrict__ mask,
                          const float*  __restrict__ cell,
                          const float*  __restrict__ offsets,
                          float*        __restrict__ out,
                          int N, int K, int rowsPer)
{
    extern __shared__ float4 s_tab[];          // N float4s (64KB for N=4096)

    const int b = blockIdx.y;

    // Cooperative table load (coalesced LDG.128 -> STS.128), once per CTA.
    const float4* gtab = g_pos4 + (size_t)b * N;
    for (int i = threadIdx.x; i < N; i += blockDim.x)
        s_tab[i] = __ldg(&gtab[i]);

    // Per-batch cell matrix -> registers (constant for whole CTA).
    const float* cb = cell + b * 9;
    const float c00 = __ldg(&cb[0]), c01 = __ldg(&cb[1]), c02 = __ldg(&cb[2]);
    const float c10 = __ldg(&cb[3]), c11 = __ldg(&cb[4]), c12 = __ldg(&cb[5]);
    const float c20 = __ldg(&cb[6]), c21 = __ldg(&cb[7]), c22 = __ldg(&cb[8]);

    __syncthreads();

    const int warp = threadIdx.x >> 5;
    const int lane = threadIdx.x & 31;

    const int r0 = blockIdx.x * rowsPer;
    const int r1 = min(r0 + rowsPer, N);

    for (int r = r0 + warp; r < r1; r += 8) {
        const float4 pi4 = s_tab[r];
        const float pix = pi4.x, piy = pi4.y, piz = pi4.z;

        // K may exceed 128 in other shape variants; loop in 128-wide chunks.
        for (int k0 = lane * 4; k0 < K; k0 += 128) {
            const long base = ((long)b * N + r) * (long)K + k0;

            const int4   nb4 = __ldcs((const int4*)  (neighbors + base));
            const float4 mk4 = __ldcs((const float4*)(mask      + base));

            const float* offp = offsets + base * 3;
            const float4 o0 = __ldcs((const float4*)(offp + 0));
            const float4 o1 = __ldcs((const float4*)(offp + 4));
            const float4 o2 = __ldcs((const float4*)(offp + 8));

            const float ox[4] = { o0.x, o0.w, o1.z, o2.y };
            const float oy[4] = { o0.y, o1.x, o1.w, o2.z };
            const float oz[4] = { o0.z, o1.y, o2.x, o2.w };
            const int   jj[4] = { nb4.x, nb4.y, nb4.z, nb4.w };
            const float mm[4] = { mk4.x, mk4.y, mk4.z, mk4.w };

            // Random gathers from SMEM table (LDS.128).
            float4 pj[4];
#pragma unroll
            for (int t = 0; t < 4; ++t)
                pj[t] = s_tab[jj[t]];

            float res[4];
#pragma unroll
            for (int t = 0; t < 4; ++t) {
                float dx = pj[t].x - pix;
                float dy = pj[t].y - piy;
                float dz = pj[t].z - piz;
                dx = fmaf(ox[t], c00, fmaf(oy[t], c10, fmaf(oz[t], c20, dx)));
                dy = fmaf(ox[t], c01, fmaf(oy[t], c11, fmaf(oz[t], c21, dy)));
                dz = fmaf(ox[t], c02, fmaf(oy[t], c12, fmaf(oz[t], c22, dz)));
                const float sq = fmaf(dx, dx, fmaf(dy, dy, dz * dz));
                res[t] = (mm[t] > 0.0f) ? sqrtf(sq) : 0.0f;
            }

            __stcs((float4*)(out + base),
                   make_float4(res[0], res[1], res[2], res[3]));
        }
    }
}

// ---------------- fallback (R2 path) for oversized N ----------------
__global__ __launch_bounds__(256)
void pairwise_dist_kernel(const int*    __restrict__ neighbors,
                          const float*  __restrict__ mask,
                          const float*  __restrict__ cell,
                          const float*  __restrict__ offsets,
                          float*        __restrict__ out,
                          int N, int K, int n_rows)
{
    const int warp = threadIdx.x >> 5;
    const int lane = threadIdx.x & 31;
    const int row  = blockIdx.x * 8 + warp;
    if (row >= n_rows) return;
    const int b = row / N;

    const float4 pi4 = __ldg(&g_pos4[row]);
    const float* cb = cell + b * 9;
    const float c00 = __ldg(&cb[0]), c01 = __ldg(&cb[1]), c02 = __ldg(&cb[2]);
    const float c10 = __ldg(&cb[3]), c11 = __ldg(&cb[4]), c12 = __ldg(&cb[5]);
    const float c20 = __ldg(&cb[6]), c21 = __ldg(&cb[7]), c22 = __ldg(&cb[8]);

    for (int k0 = lane * 4; k0 < K; k0 += 128) {
        const long base = (long)row * K + k0;
        const int4   nb4 = __ldcs((const int4*)  (neighbors + base));
        const float4 mk4 = __ldcs((const float4*)(mask      + base));
        const float* offp = offsets + base * 3;
        const float4 o0 = __ldcs((const float4*)(offp + 0));
        const float4 o1 = __ldcs((const float4*)(offp + 4));
        const float4 o2 = __ldcs((const float4*)(offp + 8));

        const float ox[4] = { o0.x, o0.w, o1.z, o2.y };
        const float oy[4] = { o0.y, o1.x, o1.w, o2.z };
        const float oz[4] = { o0.z, o1.y, o2.x, o2.w };
        const int   jj[4] = { nb4.x, nb4.y, nb4.z, nb4.w };
        const float mm[4] = { mk4.x, mk4.y, mk4.z, mk4.w };

        const float4* posb4 = g_pos4 + (long)b * N;
        float4 pj[4];
#pragma unroll
        for (int t = 0; t < 4; ++t) pj[t] = __ldg(&posb4[jj[t]]);

        float res[4];
#pragma unroll
        for (int t = 0; t < 4; ++t) {
            float dx = pj[t].x - pi4.x;
            float dy = pj[t].y - pi4.y;
            float dz = pj[t].z - pi4.z;
            dx = fmaf(ox[t], c00, fmaf(oy[t], c10, fmaf(oz[t], c20, dx)));
            dy = fmaf(ox[t], c01, fmaf(oy[t], c11, fmaf(oz[t], c21, dy)));
            dz = fmaf(ox[t], c02, fmaf(oy[t], c12, fmaf(oz[t], c22, dz)));
            res[t] = (mm[t] > 0.0f) ? sqrtf(fmaf(dx, dx, fmaf(dy, dy, dz * dz))) : 0.0f;
        }
        __stcs((float4*)(out + base), make_float4(res[0], res[1], res[2], res[3]));
    }
}

extern "C" void kernel_launch(void* const* d_in, const int* in_sizes, int n_in,
                              void* d_out, int out_size)
{
    const float* positions = (const float*)d_in[0];
    const int*   neighbors = (const int*)  d_in[1];
    const float* mask      = (const float*)d_in[2];
    const float* cell      = (const float*)d_in[3];
    const float* offsets   = (const float*)d_in[4];
    float*       out       = (float*)d_out;

    const int B      = in_sizes[3] / 9;
    const int n_rows = in_sizes[0] / 3;      // B*N
    const int N      = n_rows / B;
    const int K      = in_sizes[1] / n_rows;

    pad_positions_kernel<<<(n_rows + 255) / 256, 256>>>(positions, n_rows);

    const size_t smem = (size_t)N * sizeof(float4);

    if (n_rows <= MAX_ROWS && smem <= 65536) {
        static bool attr_set = false;
        if (!attr_set) {
            cudaFuncSetAttribute(pairwise_smem_kernel,
                                 cudaFuncAttributeMaxDynamicSharedMemorySize, 65536);
            attr_set = true;
        }
        // 3 CTAs/SM * 148 SMs = 444; pick S = floor(444/B) for one full wave.
        int S = 444 / B; if (S < 1) S = 1;
        const int rowsPer = (N + S - 1) / S;
        dim3 grid(S, B);
        pairwise_smem_kernel<<<grid, 256, smem>>>(neighbors, mask, cell,
                                                  offsets, out, N, K, rowsPer);
    } else {
        const int grid = (n_rows + 7) / 8;
        pairwise_dist_kernel<<<grid, 256>>>(neighbors, mask, cell,
                                            offsets, out, N, K, n_rows);
    }
}

// round 4
// speedup vs baseline: 1.2861x; 1.0746x over previous
#include <cuda_runtime.h>
#include <cuda_bf16.h>
#include <cstdint>

// PairwiseRepresentation: masked periodic pairwise distances.
//   positions      [B,N,3]   f32
//   neighbors      [B,N,K]   i32
//   neighbor_mask  [B,N,K]   f32
//   cell           [B,3,3]   f32
//   cell_offsets   [B,N,K,3] f32
//   out            [B,N,K]   f32
//
// R4: (1) padding fused into the CTA's smem table fill — no prologue kernel;
//     (2) 512-thread CTAs, __launch_bounds__(512,2) -> 32 warps/SM (was 24)
//         to attack the latency/occupancy limit seen in R3 (occ 34%, issue 28%).
// Gathers remain random LDS.128 from the per-batch 64KB smem table.

#define MAX_ROWS (16 * 4096)
__device__ float4 g_pos4[MAX_ROWS];   // scratch for the fallback path only

__global__ __launch_bounds__(256)
void pad_positions_kernel(const float* __restrict__ positions, int n_rows)
{
    int i = blockIdx.x * blockDim.x + threadIdx.x;
    if (i < n_rows && i < MAX_ROWS) {
        g_pos4[i] = make_float4(positions[i * 3 + 0],
                                positions[i * 3 + 1],
                                positions[i * 3 + 2], 0.0f);
    }
}

// ---------------- main kernel: smem position table ----------------
__global__ __launch_bounds__(512, 2)
void pairwise_smem_kernel(const float*  __restrict__ positions,
                          const int*    __restrict__ neighbors,
                          const float*  __restrict__ mask,
                          const float*  __restrict__ cell,
                          const float*  __restrict__ offsets,
                          float*        __restrict__ out,
                          int N, int K, int rowsPer)
{
    extern __shared__ float4 s_tab[];          // N float4s (64KB for N=4096)

    const int b = blockIdx.y;

    // Fused pad + table fill: read [N,3] f32 coalesced, write float4 smem.
    const float* pb = positions + (size_t)b * N * 3;
    for (int i = threadIdx.x; i < N; i += blockDim.x)
        s_tab[i] = make_float4(__ldg(&pb[i * 3 + 0]),
                               __ldg(&pb[i * 3 + 1]),
                               __ldg(&pb[i * 3 + 2]), 0.0f);

    // Per-batch cell matrix -> registers (constant for whole CTA).
    const float* cb = cell + b * 9;
    const float c00 = __ldg(&cb[0]), c01 = __ldg(&cb[1]), c02 = __ldg(&cb[2]);
    const float c10 = __ldg(&cb[3]), c11 = __ldg(&cb[4]), c12 = __ldg(&cb[5]);
    const float c20 = __ldg(&cb[6]), c21 = __ldg(&cb[7]), c22 = __ldg(&cb[8]);

    __syncthreads();

    const int warp    = threadIdx.x >> 5;      // 0..15
    const int lane    = threadIdx.x & 31;
    const int n_warps = blockDim.x >> 5;

    const int r0 = blockIdx.x * rowsPer;
    const int r1 = min(r0 + rowsPer, N);

    for (int r = r0 + warp; r < r1; r += n_warps) {
        const float4 pi4 = s_tab[r];
        const float pix = pi4.x, piy = pi4.y, piz = pi4.z;

        // K may exceed 128 in shape variants; loop in 128-wide chunks.
        for (int k0 = lane * 4; k0 < K; k0 += 128) {
            const long base = ((long)b * N + r) * (long)K + k0;

            const int4   nb4 = __ldcs((const int4*)  (neighbors + base));
            const float4 mk4 = __ldcs((const float4*)(mask      + base));

            const float* offp = offsets + base * 3;
            const float4 o0 = __ldcs((const float4*)(offp + 0));
            const float4 o1 = __ldcs((const float4*)(offp + 4));
            const float4 o2 = __ldcs((const float4*)(offp + 8));

            const float ox[4] = { o0.x, o0.w, o1.z, o2.y };
            const float oy[4] = { o0.y, o1.x, o1.w, o2.z };
            const float oz[4] = { o0.z, o1.y, o2.x, o2.w };
            const int   jj[4] = { nb4.x, nb4.y, nb4.z, nb4.w };
            const float mm[4] = { mk4.x, mk4.y, mk4.z, mk4.w };

            // Random gathers from SMEM table (LDS.128).
            float4 pj[4];
#pragma unroll
            for (int t = 0; t < 4; ++t)
                pj[t] = s_tab[jj[t]];

            float res[4];
#pragma unroll
            for (int t = 0; t < 4; ++t) {
                float dx = pj[t].x - pix;
                float dy = pj[t].y - piy;
                float dz = pj[t].z - piz;
                dx = fmaf(ox[t], c00, fmaf(oy[t], c10, fmaf(oz[t], c20, dx)));
                dy = fmaf(ox[t], c01, fmaf(oy[t], c11, fmaf(oz[t], c21, dy)));
                dz = fmaf(ox[t], c02, fmaf(oy[t], c12, fmaf(oz[t], c22, dz)));
                const float sq = fmaf(dx, dx, fmaf(dy, dy, dz * dz));
                res[t] = (mm[t] > 0.0f) ? sqrtf(sq) : 0.0f;
            }

            __stcs((float4*)(out + base),
                   make_float4(res[0], res[1], res[2], res[3]));
        }
    }
}

// ---------------- fallback (global-gather) for oversized N ----------------
__global__ __launch_bounds__(256)
void pairwise_dist_kernel(const int*    __restrict__ neighbors,
                          const float*  __restrict__ mask,
                          const float*  __restrict__ cell,
                          const float*  __restrict__ offsets,
                          float*        __restrict__ out,
                          int N, int K, int n_rows)
{
    const int warp = threadIdx.x >> 5;
    const int lane = threadIdx.x & 31;
    const int row  = blockIdx.x * 8 + warp;
    if (row >= n_rows) return;
    const int b = row / N;

    const float4 pi4 = __ldg(&g_pos4[row]);
    const float* cb = cell + b * 9;
    const float c00 = __ldg(&cb[0]), c01 = __ldg(&cb[1]), c02 = __ldg(&cb[2]);
    const float c10 = __ldg(&cb[3]), c11 = __ldg(&cb[4]), c12 = __ldg(&cb[5]);
    const float c20 = __ldg(&cb[6]), c21 = __ldg(&cb[7]), c22 = __ldg(&cb[8]);

    for (int k0 = lane * 4; k0 < K; k0 += 128) {
        const long base = (long)row * K + k0;
        const int4   nb4 = __ldcs((const int4*)  (neighbors + base));
        const float4 mk4 = __ldcs((const float4*)(mask      + base));
        const float* offp = offsets + base * 3;
        const float4 o0 = __ldcs((const float4*)(offp + 0));
        const float4 o1 = __ldcs((const float4*)(offp + 4));
        const float4 o2 = __ldcs((const float4*)(offp + 8));

        const float ox[4] = { o0.x, o0.w, o1.z, o2.y };
        const float oy[4] = { o0.y, o1.x, o1.w, o2.z };
        const float oz[4] = { o0.z, o1.y, o2.x, o2.w };
        const int   jj[4] = { nb4.x, nb4.y, nb4.z, nb4.w };
        const float mm[4] = { mk4.x, mk4.y, mk4.z, mk4.w };

        const float4* posb4 = g_pos4 + (long)b * N;
        float4 pj[4];
#pragma unroll
        for (int t = 0; t < 4; ++t) pj[t] = __ldg(&posb4[jj[t]]);

        float res[4];
#pragma unroll
        for (int t = 0; t < 4; ++t) {
            float dx = pj[t].x - pi4.x;
            float dy = pj[t].y - pi4.y;
            float dz = pj[t].z - pi4.z;
            dx = fmaf(ox[t], c00, fmaf(oy[t], c10, fmaf(oz[t], c20, dx)));
            dy = fmaf(ox[t], c01, fmaf(oy[t], c11, fmaf(oz[t], c21, dy)));
            dz = fmaf(ox[t], c02, fmaf(oy[t], c12, fmaf(oz[t], c22, dz)));
            res[t] = (mm[t] > 0.0f) ? sqrtf(fmaf(dx, dx, fmaf(dy, dy, dz * dz))) : 0.0f;
        }
        __stcs((float4*)(out + base), make_float4(res[0], res[1], res[2], res[3]));
    }
}

extern "C" void kernel_launch(void* const* d_in, const int* in_sizes, int n_in,
                              void* d_out, int out_size)
{
    const float* positions = (const float*)d_in[0];
    const int*   neighbors = (const int*)  d_in[1];
    const float* mask      = (const float*)d_in[2];
    const float* cell      = (const float*)d_in[3];
    const float* offsets   = (const float*)d_in[4];
    float*       out       = (float*)d_out;

    const int B      = in_sizes[3] / 9;
    const int n_rows = in_sizes[0] / 3;      // B*N
    const int N      = n_rows / B;
    const int K      = in_sizes[1] / n_rows;

    const size_t smem = (size_t)N * sizeof(float4);

    if (smem <= 65536) {
        static bool attr_set = false;
        if (!attr_set) {
            cudaFuncSetAttribute(pairwise_smem_kernel,
                                 cudaFuncAttributeMaxDynamicSharedMemorySize, 65536);
            attr_set = true;
        }
        // 2 CTAs/SM * 148 SMs = 296 target; S CTAs per batch.
        int S = 296 / B; if (S < 1) S = 1;
        const int rowsPer = (N + S - 1) / S;
        dim3 grid(S, B);
        pairwise_smem_kernel<<<grid, 512, smem>>>(positions, neighbors, mask,
                                                  cell, offsets, out, N, K, rowsPer);
    } else {
        pad_positions_kernel<<<(n_rows + 255) / 256, 256>>>(positions, n_rows);
        const int grid = (n_rows + 7) / 8;
        pairwise_dist_kernel<<<grid, 256>>>(neighbors, mask, cell,
                                            offsets, out, N, K, n_rows);
    }
}